// round 14
// baseline (speedup 1.0000x reference)
#include <cuda_runtime.h>
#include <cstdint>

#define NVEH 16384
#define NT   256
#define H    20

#define VPC  32                 // vehicles per CTA
#define TPC  160                // 4 grps x 40 threads (20 units x 2 chains)
#define NCTA (NVEH / VPC)       // 512
#define VPT  8                  // vehicles per thread-group
#define RSU  26                 // ull stride per vehicle row (24 used + 2 pad)

typedef unsigned long long ull;

// Per-unit packed weights (same as R12 champion layout):
//  slot 0..23: IF pairs (0..2 = W rows, 3 = zero pad, 4..23 = U rows)
//  slot 24..47: GO pairs, slot 48 = bias IF, 49 = bias GO
__device__ float2 gWt[20 * 50];
__device__ float  gWd[24];      // Wd[0..19], bd at [20]

// ---------- packed f32x2 helpers ----------
__device__ __forceinline__ void ffma2(ull& d, ull a, ull b) {
    asm("fma.rn.f32x2 %0, %1, %2, %0;" : "+l"(d) : "l"(a), "l"(b));
}
__device__ __forceinline__ ull pack2(float lo, float hi) {
    ull r; asm("mov.b64 %0, {%1, %2};" : "=l"(r) : "f"(lo), "f"(hi)); return r;
}
__device__ __forceinline__ float lo32(ull v) {
    float f; asm("{ .reg .b32 hi; mov.b64 {%0, hi}, %1; }" : "=f"(f) : "l"(v)); return f;
}
__device__ __forceinline__ float hi32(ull v) {
    float f; asm("{ .reg .b32 lo; mov.b64 {lo, %0}, %1; }" : "=f"(f) : "l"(v)); return f;
}
__device__ __forceinline__ float fast_tanh(float x) {
    float y; asm("tanh.approx.f32 %0, %1;" : "=f"(y) : "f"(x)); return y;
}
__device__ __forceinline__ float fast_sig(float x) {
    return fmaf(0.5f, fast_tanh(0.5f * x), 0.5f);
}

// ---------- repack (identical to R12) ----------
__global__ void repack_kernel(const float* __restrict__ W,
                              const float* __restrict__ U,
                              const float* __restrict__ b,
                              const float* __restrict__ Wd,
                              const float* __restrict__ bd)
{
    int i = blockIdx.x * blockDim.x + threadIdx.x;
    if (i < 20 * 50) {
        int u = i / 50, s = i % 50;
        float a0 = 0.f, a1 = 0.f;
        if (s < 24) {                       // IF pair, slot s
            if (s < 3)       { a0 = W[s * 80 + u];        a1 = W[s * 80 + 20 + u]; }
            else if (s >= 4) { a0 = U[(s - 4) * 80 + u];  a1 = U[(s - 4) * 80 + 20 + u]; }
        } else if (s < 48) {                // GO pair, slot s-24
            int k = s - 24;
            if (k < 3)       { a0 = W[k * 80 + 40 + u];       a1 = W[k * 80 + 60 + u]; }
            else if (k >= 4) { a0 = U[(k - 4) * 80 + 40 + u]; a1 = U[(k - 4) * 80 + 60 + u]; }
        } else if (s == 48)  { a0 = b[u];      a1 = b[20 + u]; }
        else                 { a0 = b[40 + u]; a1 = b[60 + u]; }
        gWt[i] = make_float2(a0, a1);
    }
    if (i < 20)  gWd[i]  = Wd[i];
    if (i == 20) gWd[20] = bd[0];
}

__global__ __launch_bounds__(TPC, 4)
void rnncf_kernel(const float* __restrict__ lead_inputs,  // (NVEH, NT, 2)
                  const float* __restrict__ init_state,   // (NVEH, 2)
                  const float* __restrict__ h0,           // (NVEH, H)
                  const float* __restrict__ c0,           // (NVEH, H)
                  float* __restrict__ out,
                  int out_size)
{
    // Double-buffered DUPLICATED activation rows (ull = (v,v) f32 pair):
    // slot 0..2 = x dup, 3 = zero pad, 4+j = h[j] dup. Stride RSU=26 ull.
    __shared__ ull xh[2][VPC * RSU];    // 2 * 32 * 26 * 8B = 13.3 KB
    __shared__ float swd[24];           // Wd + bd for drivers

    const int tid = threadIdx.x;
    const int grp = tid / 40;          // 0..3
    const int r   = tid % 40;
    const int u   = r >> 1;            // unit 0..19
    const int ch  = r & 1;             // 0 = IF chain, 1 = GO chain
    const int vb  = grp * VPT;

    // ---- this thread's chain weights (24 ull + bias) ----
    ull wC[24], bC;
    {
        const ull* tb = reinterpret_cast<const ull*>(gWt) + u * 50 + ch * 24;
#pragma unroll
        for (int k = 0; k < 24; ++k) wC[k] = tb[k];
        bC = reinterpret_cast<const ull*>(gWt)[u * 50 + 48 + ch];
    }
    if (tid < 24) swd[tid] = gWd[tid];

    // per-chain activation constants for the accumulator's lo half:
    //  IF: sig -> tanh(0.5x)*0.5+0.5 ;  GO: tanh -> tanh(x)*1+0
    const float s0 = ch ? 1.0f : 0.5f;
    const float k0 = ch ? 1.0f : 0.5f;
    const float c0a = ch ? 0.0f : 0.5f;

    // zero pad slot of every row in both buffers
    for (int i = tid; i < VPC; i += TPC) {
        xh[0][i * RSU + 3] = 0ull;
        xh[1][i * RSU + 3] = 0ull;
    }

    // ---- init state ----
    float cc[VPT];                      // live on GO threads
#pragma unroll
    for (int v = 0; v < VPT; ++v) {
        int gveh = blockIdx.x * VPC + vb + v;
        if (ch) {
            cc[v] = c0[gveh * H + u];
        } else {
            float hv = h0[gveh * H + u];
            xh[0][(vb + v) * RSU + 4 + u] = pack2(hv, hv);
        }
    }

    // driver-only state (threads 0..31 = warp 0)
    float pos = 0.f, spd = 0.f;
    const float2* mylead = nullptr;
    if (tid < VPC) {
        int gveh = blockIdx.x * VPC + tid;
        pos = init_state[2 * gveh];
        spd = init_state[2 * gveh + 1];
        mylead = reinterpret_cast<const float2*>(lead_inputs) + (size_t)gveh * NT;
        float2 l0 = mylead[0];
        float x0 = (l0.x - pos) * 0.01f;
        float x1 = spd * 0.025f;
        float x2 = l0.y * 0.025f;
        xh[0][tid * RSU + 0] = pack2(x0, x0);
        xh[0][tid * RSU + 1] = pack2(x1, x1);
        xh[0][tid * RSU + 2] = pack2(x2, x2);
    }
    __syncthreads();

    const bool write_extras = (out_size >= NT * NVEH + NVEH + 2 * NVEH * H);
    float* outbase = out + blockIdx.x * VPC + tid;

#pragma unroll 1
    for (int t = 0; t < NT; ++t) {
        const ull* rb = xh[t & 1];
        ull*       wb = xh[(t + 1) & 1];

        // driver prefetch of lead[t+1]
        float2 nl = make_float2(0.f, 0.f);
        if (tid < VPC) {
            int tn = (t + 1 < NT) ? (t + 1) : (NT - 1);
            nl = mylead[tn];
        }

        // ---- GEMM + gates for this thread's 8 vehicles (one chain each) ----
#pragma unroll 2
        for (int v = 0; v < VPT; ++v) {
            const ulonglong2* row =
                reinterpret_cast<const ulonglong2*>(rb + (vb + v) * RSU);
            ull acc = bC;
#pragma unroll
            for (int j = 0; j < 12; ++j) {
                ulonglong2 m = row[j];       // two dup'd multipliers
                ffma2(acc, wC[2 * j],     m.x);
                ffma2(acc, wC[2 * j + 1], m.y);
            }
            // activations: IF -> (sig(i), sig(f)); GO -> (tanh(g), sig(o))
            float e0 = fmaf(k0, fast_tanh(s0 * lo32(acc)), c0a);
            float e1 = fast_sig(hi32(acc));
            ull pay  = pack2(e0, e1);
            ull peer = __shfl_xor_sync(0xffffffffu, pay, 1);
            if (ch) {
                float si = lo32(peer);       // sig(i) from IF thread
                float sf = hi32(peer);       // sig(f)
                float cn = fmaf(sf, cc[v], si * e0);   // e0 = tanh(g)
                cc[v] = cn;
                float hn = e1 * fast_tanh(cn);          // e1 = sig(o)
                wb[(vb + v) * RSU + 4 + u] = pack2(hn, hn);
            }
        }
        __syncthreads();

        // ---- driver phase: Wd dot on h(t+1), pos/spd, out, x(t+1) ----
        if (tid < VPC) {
            const float* hrow =
                reinterpret_cast<const float*>(wb + tid * RSU) + 8;  // dup'd h
            float sa = swd[20], sb = 0.f;
#pragma unroll
            for (int j = 0; j < 10; ++j) {
                float4 f = reinterpret_cast<const float4*>(hrow)[j]; // (h2j,h2j,h2j+1,h2j+1)
                sa = fmaf(f.x, swd[2 * j],     sa);
                sb = fmaf(f.z, swd[2 * j + 1], sb);
            }
            float a = fmaf(7.0f, sa + sb, -4.0f);   // (MAXA-MINA)*out + MINA
            spd = fmaf(0.1f, a, spd);
            pos = fmaf(0.1f, a, pos);
            outbase[(size_t)t * NVEH] = pos;
            float x0 = (nl.x - pos) * 0.01f;
            float x1 = spd * 0.025f;
            float x2 = nl.y * 0.025f;
            wb[tid * RSU + 0] = pack2(x0, x0);
            wb[tid * RSU + 1] = pack2(x1, x1);
            wb[tid * RSU + 2] = pack2(x2, x2);
        }
        __syncthreads();
    }

    if (write_extras) {
        if (tid < VPC)
            out[(size_t)NT * NVEH + blockIdx.x * VPC + tid] = spd;
        float* hout = out + (size_t)NT * NVEH + NVEH;
        float* cout = hout + (size_t)NVEH * H;
        const ull* fb = xh[NT & 1];   // h(256) lives in buf[0]
#pragma unroll
        for (int v = 0; v < VPT; ++v) {
            int gveh = blockIdx.x * VPC + vb + v;
            if (ch) {
                hout[gveh * H + u] = lo32(fb[(vb + v) * RSU + 4 + u]);
                cout[gveh * H + u] = cc[v];
            }
        }
    }
}

extern "C" void kernel_launch(void* const* d_in, const int* in_sizes, int n_in,
                              void* d_out, int out_size) {
    const float* lead_inputs = (const float*)d_in[0];
    const float* init_state  = (const float*)d_in[1];
    const float* h0          = (const float*)d_in[2];
    const float* c0          = (const float*)d_in[3];
    const float* W           = (const float*)d_in[4];
    const float* U           = (const float*)d_in[5];
    const float* b           = (const float*)d_in[6];
    const float* Wd          = (const float*)d_in[7];
    const float* bd          = (const float*)d_in[8];

    repack_kernel<<<1, 1024>>>(W, U, b, Wd, bd);
    rnncf_kernel<<<NCTA, TPC>>>(lead_inputs, init_state, h0, c0,
                                (float*)d_out, out_size);
}